// round 5
// baseline (speedup 1.0000x reference)
#include <cuda_runtime.h>
#include <cuda_bf16.h>
#include <cstdint>

// ============================================================================
// Arch gating: tcgen05/TMEM are sm_103a ("arch-specific") features. The
// harness also compiles a plain compute_103 stage, which must not see any
// tcgen05 PTX. HAS_TC selects the real tensor-core path only on the
// arch-specific device pass; all other passes get a correct FFMA fallback.
// ============================================================================
#if defined(__CUDA_ARCH__) && \
    (defined(__CUDA_ARCH_FEAT_SM103_ALL) || defined(__CUDA_ARCH_FEAT_SM100_ALL) || \
     defined(__CUDA_ARCH_SPECIFIC__) || defined(__CUDA_ARCH_FAMILY_SPECIFIC__))
#define HAS_TC 1
#else
#define HAS_TC 0
#endif

// ============================================================================
// Problem constants: B=8192 (derived at launch), U=16, I=H=128, 3H=384 gates
// ============================================================================
#define U_DIM 16
#define I_DIM 128
#define H_DIM 128
#define G3    384
#define W_ELEMS (U_DIM * G3 * I_DIM)   // 786432 per weight matrix

// Pre-split weights (fp32 -> bf16 hi + bf16 lo), filled by prep kernel.
__device__ __nv_bfloat16 g_wih_hi[W_ELEMS];
__device__ __nv_bfloat16 g_wih_lo[W_ELEMS];
__device__ __nv_bfloat16 g_whh_hi[W_ELEMS];
__device__ __nv_bfloat16 g_whh_lo[W_ELEMS];

// ============================================================================
// PTX helpers
// ============================================================================
__device__ __forceinline__ uint32_t elect_one_pred() {
    uint32_t pred;
    asm volatile(
        "{\n\t"
        ".reg .pred p;\n\t"
        "elect.sync _|p, 0xFFFFFFFF;\n\t"
        "selp.b32 %0, 1, 0, p;\n\t"
        "}"
        : "=r"(pred));
    return pred;
}

__device__ __forceinline__ uint32_t smem_to_u32(const void* smem_ptr) {
    uint32_t addr;
    asm("{ .reg .u64 tmp; cvta.to.shared.u64 tmp, %1; cvt.u32.u64 %0, tmp; }"
        : "=r"(addr) : "l"(smem_ptr));
    return addr;
}

#define SMEM_SWIZZLE_128B(byte_offset) \
    ((byte_offset) ^ (((byte_offset) >> 3) & 0x70))

static constexpr uint64_t SMEM_DESC_BASE_SW128 =
    (uint64_t(2)  << 61)    // layout_type = SW128
    | (uint64_t(1) << 46)   // version = 1 (Blackwell)
    | (uint64_t(64) << 32)  // SBO = 64 (1024B per 8-row group)
    | (uint64_t(1) << 16);  // LBO = 1

#define MAKE_SMEM_DESC(base_addr) \
    (SMEM_DESC_BASE_SW128 | ((uint64_t)((base_addr) >> 4) & 0x3FFF))

#define TCGEN05_ALLOC(smem_result_addr, nCols) \
    asm volatile( \
        "tcgen05.alloc.cta_group::1.sync.aligned.shared::cta.b32 [%0], %1;" \
        :: "r"((uint32_t)(smem_result_addr)), "r"((uint32_t)(nCols)) \
        : "memory")

#define TCGEN05_DEALLOC(tmem_addr, nCols) \
    asm volatile( \
        "tcgen05.dealloc.cta_group::1.sync.aligned.b32 %0, %1;" \
        :: "r"(tmem_addr), "r"((uint32_t)(nCols)))

#define TCGEN05_RELINQUISH_ALLOC_PERMIT() \
    asm volatile("tcgen05.relinquish_alloc_permit.cta_group::1.sync.aligned;")

#define TCGEN05_COMMIT(mbar_smem_addr) \
    asm volatile( \
        "tcgen05.commit.cta_group::1.mbarrier::arrive::one.shared::cluster.b64 [%0];" \
        :: "r"((uint32_t)(mbar_smem_addr)) \
        : "memory")

#define TCGEN05_FENCE_AFTER() \
    asm volatile("tcgen05.fence::after_thread_sync;" ::: "memory")

#define TCGEN05_FENCE_BEFORE() \
    asm volatile("tcgen05.fence::before_thread_sync;" ::: "memory")

#define TCGEN05_WAIT_LD() \
    asm volatile("tcgen05.wait::ld.sync.aligned;" ::: "memory")

#define FENCE_PROXY_ASYNC_SHARED_CTA() \
    asm volatile("fence.proxy.async.shared::cta;" ::: "memory")

#define MBARRIER_INIT(mbar_smem_addr, count) \
    asm volatile( \
        "mbarrier.init.shared.b64 [%0], %1;" \
        :: "r"((uint32_t)(mbar_smem_addr)), "r"((uint32_t)(count)) \
        : "memory")

#define MBARRIER_WAIT_PARITY(mbar_smem_addr, phase_parity) do { \
    uint32_t _mbar = (uint32_t)(mbar_smem_addr); \
    uint32_t _parity = (uint32_t)(phase_parity); \
    uint32_t _done; \
    asm volatile( \
        "{\n\t" \
        ".reg .pred p;\n\t" \
        "mbarrier.try_wait.parity.acquire.cta.shared::cta.b64 p, [%1], %2;\n\t" \
        "selp.b32 %0, 1, 0, p;\n\t" \
        "}" \
        : "=r"(_done) : "r"(_mbar), "r"(_parity) : "memory"); \
    if (!_done) { \
        asm volatile( \
            "{\n\t" \
            ".reg .pred P1;\n\t" \
            "WAIT_LOOP_%=:\n\t" \
            "mbarrier.try_wait.parity.acquire.cta.shared::cta.b64 P1, [%0], %1, 0x989680;\n\t" \
            "@P1 bra.uni WAIT_DONE_%=;\n\t" \
            "bra.uni WAIT_LOOP_%=;\n\t" \
            "WAIT_DONE_%=:\n\t" \
            "}" \
            :: "r"(_mbar), "r"(_parity) : "memory"); \
    } \
} while(0)

#define TCGEN05_LD_32X32B_X16(r, tmem_addr) \
    asm volatile( \
        "tcgen05.ld.sync.aligned.32x32b.x16.b32 " \
        "{%0, %1, %2, %3, %4, %5, %6, %7, " \
        " %8, %9, %10, %11, %12, %13, %14, %15}, [%16];" \
        : "=r"((r)[0]),  "=r"((r)[1]),  "=r"((r)[2]),  "=r"((r)[3]), \
          "=r"((r)[4]),  "=r"((r)[5]),  "=r"((r)[6]),  "=r"((r)[7]), \
          "=r"((r)[8]),  "=r"((r)[9]),  "=r"((r)[10]), "=r"((r)[11]), \
          "=r"((r)[12]), "=r"((r)[13]), "=r"((r)[14]), "=r"((r)[15]) \
        : "r"(tmem_addr))

#if HAS_TC
// SS-mode cg1 bf16 MMA (kind::f16), fp32 accumulate in TMEM.
__device__ __forceinline__ void mma_f16_ss(uint32_t d_tmem, uint64_t a_desc,
                                           uint64_t b_desc, uint32_t idesc,
                                           uint32_t en) {
    asm volatile(
        "{\n\t"
        ".reg .pred p;\n\t"
        "setp.ne.u32 p, %5, 0;\n\t"
        "tcgen05.mma.cta_group::1.kind::f16 [%0], %1, %2, %3, {%4, %4, %4, %4}, p;\n\t"
        "}"
        :: "r"(d_tmem), "l"(a_desc), "l"(b_desc), "r"(idesc), "r"(0u), "r"(en)
        : "memory");
}
#endif

// ============================================================================
// Shared memory layout (all MMA buffers 1024B-aligned for SW128 descriptors)
// ============================================================================
static constexpr int SMEM_TMEMPTR = 0;
static constexpr int SMEM_MBAR    = 8;
static constexpr int SMEM_BIAS    = 16;      // 512 floats (rz_sum | xn_b | hn_b)
static constexpr int SMEM_A_HI    = 4096;    // 128 rows x 128B  = 16 KB
static constexpr int SMEM_A_LO    = 20480;   // 16 KB
static constexpr int SMEM_B_HI    = 36864;   // 384 rows x 128B  = 48 KB
static constexpr int SMEM_B_LO    = 86016;   // 48 KB
static constexpr int SMEM_TOTAL   = 135168;  // 132 KB

// idesc kind::f16: dtype=F32, atype=btype=BF16, N=128, M=128 (cg1)
static constexpr uint32_t IDESC =
    (1u << 4) | (1u << 7) | (1u << 10) | ((128u / 8) << 17) | ((128u / 16) << 24);

// ============================================================================
// Prep kernel: split fp32 weights into bf16 hi/lo pairs
// ============================================================================
__global__ void __launch_bounds__(256) gru_prep(const float* __restrict__ w_ih,
                                                const float* __restrict__ w_hh) {
    int i = blockIdx.x * 256 + threadIdx.x;
    if (i >= W_ELEMS) return;
    float v = w_ih[i];
    __nv_bfloat16 h = __float2bfloat16(v);
    g_wih_hi[i] = h;
    g_wih_lo[i] = __float2bfloat16(v - __bfloat162float(h));
    v = w_hh[i];
    h = __float2bfloat16(v);
    g_whh_hi[i] = h;
    g_whh_lo[i] = __float2bfloat16(v - __bfloat162float(h));
}

// ============================================================================
// Main fused GRU kernel. One CTA = (u, 128-row batch tile).
// TMEM D layout: [0:128)=r_sum  [128:256)=z_sum  [256:384)=xn  [384:512)=hn
// ============================================================================
__global__ void __launch_bounds__(128, 1) gru_main(
    const float* __restrict__ inputs,
    const float* __restrict__ hidden,
    const float* __restrict__ w_ih,
    const float* __restrict__ w_hh,
    const float* __restrict__ b_ih,
    const float* __restrict__ b_hh,
    float* __restrict__ out)
{
    extern __shared__ __align__(1024) char smem[];
    const int tid = threadIdx.x;
    const int u   = blockIdx.y;
    const int b0  = blockIdx.x * 128;

#if HAS_TC
    const uint32_t smem_base = smem_to_u32(smem);
    const int wid = tid >> 5;

    // TMEM alloc (512 cols) + mbarrier init + bias preload
    if (wid == 0) {
        TCGEN05_ALLOC(smem_base + SMEM_TMEMPTR, 512);
        TCGEN05_RELINQUISH_ALLOC_PERMIT();
    }
    if (tid == 0) MBARRIER_INIT(smem_base + SMEM_MBAR, 1);

    float* bias = (float*)(smem + SMEM_BIAS);
    for (int g = tid; g < G3; g += 128) {
        float bi = b_ih[u * G3 + g];
        float bh = b_hh[u * G3 + g];
        if (g < 256) {
            bias[g] = bi + bh;          // r,z: biases fold into the summed gate
        } else {
            bias[g]       = bi;         // [256:384) xn bias
            bias[g + 128] = bh;         // [384:512) hn bias
        }
    }
    __syncthreads();

    uint32_t tmem_base;
    asm volatile("ld.shared.b32 %0, [%1];"
                 : "=r"(tmem_base) : "r"(smem_base + SMEM_TMEMPTR));

    // ---------------- mainloop: 2 phases (x-side, h-side) x 2 K-chunks -------
    int gc = 0;
    for (int ph = 0; ph < 2; ph++) {
        const float* asrc = ph ? hidden : inputs;
        const __nv_bfloat16* wh = ph ? g_whh_hi : g_wih_hi;
        const __nv_bfloat16* wl = ph ? g_whh_lo : g_wih_lo;
        for (int cc = 0; cc < 2; cc++, gc++) {
            const int k0 = cc * 64;

            // A tile: 128 rows x 64 fp32 -> bf16 hi/lo, SW128 swizzled smem
            for (int q = tid; q < 2048; q += 128) {
                const int row  = q >> 4;
                const int colf = (q & 15) << 2;
                const float4 v = *(const float4*)(asrc +
                    (((size_t)(b0 + row)) * U_DIM + u) * I_DIM + k0 + colf);
                __nv_bfloat162 h0 = __float22bfloat162_rn(make_float2(v.x, v.y));
                __nv_bfloat162 h1 = __float22bfloat162_rn(make_float2(v.z, v.w));
                float2 r0 = make_float2(v.x - __bfloat162float(h0.x),
                                        v.y - __bfloat162float(h0.y));
                float2 r1 = make_float2(v.z - __bfloat162float(h1.x),
                                        v.w - __bfloat162float(h1.y));
                __nv_bfloat162 l0 = __float22bfloat162_rn(r0);
                __nv_bfloat162 l1 = __float22bfloat162_rn(r1);
                const uint32_t off =
                    SMEM_SWIZZLE_128B((uint32_t)(row * 128 + colf * 2));
                *(uint2*)(smem + SMEM_A_HI + off) =
                    make_uint2(*(uint32_t*)&h0, *(uint32_t*)&h1);
                *(uint2*)(smem + SMEM_A_LO + off) =
                    make_uint2(*(uint32_t*)&l0, *(uint32_t*)&l1);
            }

            // B tile: 384 gate rows x 64 bf16 cols (hi + lo), SW128 swizzled
            for (int q = tid; q < 3072; q += 128) {
                const int row = q >> 3;
                const int ce  = (q & 7) << 3;     // element col
                const size_t gi = (((size_t)u * G3) + row) * I_DIM + k0 + ce;
                const uint4 vh = *(const uint4*)(wh + gi);
                const uint4 vl = *(const uint4*)(wl + gi);
                const uint32_t off =
                    SMEM_SWIZZLE_128B((uint32_t)(row * 128 + ce * 2));
                *(uint4*)(smem + SMEM_B_HI + off) = vh;
                *(uint4*)(smem + SMEM_B_LO + off) = vl;
            }

            FENCE_PROXY_ASYNC_SHARED_CTA();
            __syncthreads();

            // MMA issue: 3 split terms x 4 K16 steps x 3 N128 tiles
            if (wid == 0) {
                if (elect_one_pred()) {
                    const uint64_t adh = MAKE_SMEM_DESC(smem_base + SMEM_A_HI);
                    const uint64_t adl = MAKE_SMEM_DESC(smem_base + SMEM_A_LO);
                    const uint64_t bdh = MAKE_SMEM_DESC(smem_base + SMEM_B_HI);
                    const uint64_t bdl = MAKE_SMEM_DESC(smem_base + SMEM_B_LO);
                    for (int term = 0; term < 3; term++) {
                        const uint64_t ad = (term == 2) ? adl : adh;
                        const uint64_t bd = (term == 1) ? bdl : bdh;
                        for (int ks = 0; ks < 4; ks++) {
                            for (int nt = 0; nt < 3; nt++) {
                                const uint32_t dcol =
                                    (ph == 1 && nt == 2) ? 384u : (uint32_t)(nt * 128);
                                uint32_t en;
                                if (ph == 0)
                                    en = (cc | term | ks) ? 1u : 0u;     // r,z,xn first touch
                                else
                                    en = (nt < 2) ? 1u
                                                  : ((cc | term | ks) ? 1u : 0u); // hn first touch
                                mma_f16_ss(tmem_base + dcol,
                                           ad + ks * 2,
                                           bd + nt * 1024 + ks * 2,
                                           IDESC, en);
                            }
                        }
                    }
                    TCGEN05_COMMIT(smem_base + SMEM_MBAR);
                }
            }
            MBARRIER_WAIT_PARITY(smem_base + SMEM_MBAR, gc & 1);
        }
    }
    TCGEN05_FENCE_AFTER();

    // ---------------- epilogue: TMEM -> GRU elementwise -> GMEM --------------
    const int row = tid;  // 128 threads = 128 M rows; warp w owns lanes 32w..32w+31
    const float* hrow = hidden + (((size_t)(b0 + row)) * U_DIM + u) * H_DIM;
    float*       orow = out    + (((size_t)(b0 + row)) * U_DIM + u) * H_DIM;

    for (int cb = 0; cb < 128; cb += 16) {
        uint32_t rr[16], zz[16], xn[16], hn[16];
        TCGEN05_LD_32X32B_X16(rr, tmem_base + cb);
        TCGEN05_LD_32X32B_X16(zz, tmem_base + 128 + cb);
        TCGEN05_LD_32X32B_X16(xn, tmem_base + 256 + cb);
        TCGEN05_LD_32X32B_X16(hn, tmem_base + 384 + cb);
        TCGEN05_WAIT_LD();

        float4 hv[4];
        const float4* hp = (const float4*)(hrow + cb);
        hv[0] = hp[0]; hv[1] = hp[1]; hv[2] = hp[2]; hv[3] = hp[3];
        const float* hvf = (const float*)hv;

        float res[16];
        #pragma unroll
        for (int j = 0; j < 16; j++) {
            const int c = cb + j;
            const float vr = __uint_as_float(rr[j]) + bias[c];
            const float vz = __uint_as_float(zz[j]) + bias[128 + c];
            const float r  = 1.f / (1.f + __expf(-vr));
            const float z  = 1.f / (1.f + __expf(-vz));
            const float vn = __uint_as_float(xn[j]) + bias[256 + c]
                           + r * (__uint_as_float(hn[j]) + bias[384 + c]);
            const float n  = tanhf(vn);
            res[j] = (1.f - z) * n + z * hvf[j];
        }
        TCGEN05_FENCE_BEFORE();
        float4* op = (float4*)(orow + cb);
        op[0] = ((float4*)res)[0];
        op[1] = ((float4*)res)[1];
        op[2] = ((float4*)res)[2];
        op[3] = ((float4*)res)[3];
    }

    __syncthreads();
    if (wid == 0) {
        TCGEN05_DEALLOC(tmem_base, 512);
    }

#else  // ---------------- fallback: plain fp32 FFMA (non-sm_103a targets) ----
    // Correct but slow; only executes if the runtime ever JITs the plain
    // compute_103 PTX instead of using the sm_103a cubin.
    float* xs = (float*)smem;              // 128 x 128
    float* hs = xs + 128 * 128;            // 128 x 128
    for (int q = tid; q < 128 * 128; q += 128) {
        const int row = q >> 7, col = q & 127;
        const size_t base = (((size_t)(b0 + row)) * U_DIM + u) * I_DIM + col;
        xs[q] = inputs[base];
        hs[q] = hidden[base];
    }
    __syncthreads();

    const float* xr_ = xs + tid * 128;
    const float* hr_ = hs + tid * 128;
    float* orow = out + (((size_t)(b0 + tid)) * U_DIM + u) * H_DIM;

    for (int c = 0; c < H_DIM; c++) {
        float axr = b_ih[u * G3 + c],       ahr = b_hh[u * G3 + c];
        float axz = b_ih[u * G3 + 128 + c], ahz = b_hh[u * G3 + 128 + c];
        float axn = b_ih[u * G3 + 256 + c], ahn = b_hh[u * G3 + 256 + c];
        const float* wir = w_ih + (((size_t)u * G3) + c) * I_DIM;
        const float* whr = w_hh + (((size_t)u * G3) + c) * I_DIM;
        for (int k = 0; k < I_DIM; k++) {
            const float xv = xr_[k], hv = hr_[k];
            axr += xv * wir[k];
            axz += xv * wir[128 * I_DIM + k];
            axn += xv * wir[256 * I_DIM + k];
            ahr += hv * whr[k];
            ahz += hv * whr[128 * I_DIM + k];
            ahn += hv * whr[256 * I_DIM + k];
        }
        const float r = 1.f / (1.f + expf(-(axr + ahr)));
        const float z = 1.f / (1.f + expf(-(axz + ahz)));
        const float n = tanhf(axn + r * ahn);
        orow[c] = (1.f - z) * n + z * hr_[c];
    }
#endif
}

// ============================================================================
// kernel_launch — graph-capturable, allocation-free
// ============================================================================
extern "C" void kernel_launch(void* const* d_in, const int* in_sizes, int n_in,
                              void* d_out, int out_size) {
    const float* inputs = (const float*)d_in[0];
    const float* hidden = (const float*)d_in[1];
    const float* w_ih   = (const float*)d_in[2];
    const float* w_hh   = (const float*)d_in[3];
    const float* b_ih   = (const float*)d_in[4];
    const float* b_hh   = (const float*)d_in[5];
    float* out = (float*)d_out;

    const int B = in_sizes[0] / (U_DIM * I_DIM);   // 8192

    gru_prep<<<(W_ELEMS + 255) / 256, 256>>>(w_ih, w_hh);

    cudaFuncSetAttribute(gru_main,
                         cudaFuncAttributeMaxDynamicSharedMemorySize, SMEM_TOTAL);
    gru_main<<<dim3(B / 128, U_DIM), 128, SMEM_TOTAL>>>(
        inputs, hidden, w_ih, w_hh, b_ih, b_hh, out);
}

// round 6
// speedup vs baseline: 1.7804x; 1.7804x over previous
#include <cuda_runtime.h>
#include <cuda_bf16.h>
#include <cstdint>

// ============================================================================
// Arch gating: tcgen05/TMEM are sm_103a ("arch-specific") features. The
// harness also compiles a plain compute_103 stage, which must not see any
// tcgen05 PTX. HAS_TC selects the real tensor-core path only on the
// arch-specific device pass; all other passes get a correct FFMA fallback.
// ============================================================================
#if defined(__CUDA_ARCH__) && \
    (defined(__CUDA_ARCH_FEAT_SM103_ALL) || defined(__CUDA_ARCH_FEAT_SM100_ALL) || \
     defined(__CUDA_ARCH_SPECIFIC__) || defined(__CUDA_ARCH_FAMILY_SPECIFIC__))
#define HAS_TC 1
#else
#define HAS_TC 0
#endif

// ============================================================================
// Problem constants: B=8192 (derived at launch), U=16, I=H=128, 3H=384 gates
// ============================================================================
#define U_DIM 16
#define I_DIM 128
#define H_DIM 128
#define G3    384
#define W_ELEMS (U_DIM * G3 * I_DIM)   // 786432 per weight matrix

// Pre-split weights (fp32 -> bf16 hi + bf16 lo), filled by prep kernel.
__device__ __nv_bfloat16 g_wih_hi[W_ELEMS];
__device__ __nv_bfloat16 g_wih_lo[W_ELEMS];
__device__ __nv_bfloat16 g_whh_hi[W_ELEMS];
__device__ __nv_bfloat16 g_whh_lo[W_ELEMS];

// ============================================================================
// PTX helpers
// ============================================================================
__device__ __forceinline__ uint32_t elect_one_pred() {
    uint32_t pred;
    asm volatile(
        "{\n\t"
        ".reg .pred p;\n\t"
        "elect.sync _|p, 0xFFFFFFFF;\n\t"
        "selp.b32 %0, 1, 0, p;\n\t"
        "}"
        : "=r"(pred));
    return pred;
}

__device__ __forceinline__ uint32_t smem_to_u32(const void* smem_ptr) {
    uint32_t addr;
    asm("{ .reg .u64 tmp; cvta.to.shared.u64 tmp, %1; cvt.u32.u64 %0, tmp; }"
        : "=r"(addr) : "l"(smem_ptr));
    return addr;
}

// SW64 swizzle: atom = 8 rows x 64 bytes
#define SMEM_SWIZZLE_64B(byte_offset) \
    ((byte_offset) ^ (((byte_offset) >> 3) & 0x30))

// SW64 smem descriptor: layout=4, version=1 (Blackwell), SBO=32 (512B per
// 8-row group), LBO=1 (16B inner stride). Rows are 64B wide.
static constexpr uint64_t SMEM_DESC_BASE_SW64 =
    (uint64_t(4)  << 61)
    | (uint64_t(1) << 46)
    | (uint64_t(32) << 32)
    | (uint64_t(1) << 16);

#define MAKE_SMEM_DESC64(base_addr) \
    (SMEM_DESC_BASE_SW64 | ((uint64_t)((base_addr) >> 4) & 0x3FFF))

#define TCGEN05_ALLOC(smem_result_addr, nCols) \
    asm volatile( \
        "tcgen05.alloc.cta_group::1.sync.aligned.shared::cta.b32 [%0], %1;" \
        :: "r"((uint32_t)(smem_result_addr)), "r"((uint32_t)(nCols)) \
        : "memory")

#define TCGEN05_DEALLOC(tmem_addr, nCols) \
    asm volatile( \
        "tcgen05.dealloc.cta_group::1.sync.aligned.b32 %0, %1;" \
        :: "r"(tmem_addr), "r"((uint32_t)(nCols)))

#define TCGEN05_RELINQUISH_ALLOC_PERMIT() \
    asm volatile("tcgen05.relinquish_alloc_permit.cta_group::1.sync.aligned;")

#define TCGEN05_COMMIT(mbar_smem_addr) \
    asm volatile( \
        "tcgen05.commit.cta_group::1.mbarrier::arrive::one.shared::cluster.b64 [%0];" \
        :: "r"((uint32_t)(mbar_smem_addr)) \
        : "memory")

#define TCGEN05_FENCE_AFTER() \
    asm volatile("tcgen05.fence::after_thread_sync;" ::: "memory")

#define TCGEN05_FENCE_BEFORE() \
    asm volatile("tcgen05.fence::before_thread_sync;" ::: "memory")

#define TCGEN05_WAIT_LD() \
    asm volatile("tcgen05.wait::ld.sync.aligned;" ::: "memory")

#define FENCE_PROXY_ASYNC_SHARED_CTA() \
    asm volatile("fence.proxy.async.shared::cta;" ::: "memory")

#define MBARRIER_INIT(mbar_smem_addr, count) \
    asm volatile( \
        "mbarrier.init.shared.b64 [%0], %1;" \
        :: "r"((uint32_t)(mbar_smem_addr)), "r"((uint32_t)(count)) \
        : "memory")

#define MBARRIER_WAIT_PARITY(mbar_smem_addr, phase_parity) do { \
    uint32_t _mbar = (uint32_t)(mbar_smem_addr); \
    uint32_t _parity = (uint32_t)(phase_parity); \
    uint32_t _done; \
    asm volatile( \
        "{\n\t" \
        ".reg .pred p;\n\t" \
        "mbarrier.try_wait.parity.acquire.cta.shared::cta.b64 p, [%1], %2;\n\t" \
        "selp.b32 %0, 1, 0, p;\n\t" \
        "}" \
        : "=r"(_done) : "r"(_mbar), "r"(_parity) : "memory"); \
    if (!_done) { \
        asm volatile( \
            "{\n\t" \
            ".reg .pred P1;\n\t" \
            "WAIT_LOOP_%=:\n\t" \
            "mbarrier.try_wait.parity.acquire.cta.shared::cta.b64 P1, [%0], %1, 0x989680;\n\t" \
            "@P1 bra.uni WAIT_DONE_%=;\n\t" \
            "bra.uni WAIT_LOOP_%=;\n\t" \
            "WAIT_DONE_%=:\n\t" \
            "}" \
            :: "r"(_mbar), "r"(_parity) : "memory"); \
    } \
} while(0)

#define TCGEN05_LD_32X32B_X16(r, tmem_addr) \
    asm volatile( \
        "tcgen05.ld.sync.aligned.32x32b.x16.b32 " \
        "{%0, %1, %2, %3, %4, %5, %6, %7, " \
        " %8, %9, %10, %11, %12, %13, %14, %15}, [%16];" \
        : "=r"((r)[0]),  "=r"((r)[1]),  "=r"((r)[2]),  "=r"((r)[3]), \
          "=r"((r)[4]),  "=r"((r)[5]),  "=r"((r)[6]),  "=r"((r)[7]), \
          "=r"((r)[8]),  "=r"((r)[9]),  "=r"((r)[10]), "=r"((r)[11]), \
          "=r"((r)[12]), "=r"((r)[13]), "=r"((r)[14]), "=r"((r)[15]) \
        : "r"(tmem_addr))

#if HAS_TC
// SS-mode cg1 bf16 MMA (kind::f16), fp32 accumulate in TMEM.
__device__ __forceinline__ void mma_f16_ss(uint32_t d_tmem, uint64_t a_desc,
                                           uint64_t b_desc, uint32_t idesc,
                                           uint32_t en) {
    asm volatile(
        "{\n\t"
        ".reg .pred p;\n\t"
        "setp.ne.u32 p, %5, 0;\n\t"
        "tcgen05.mma.cta_group::1.kind::f16 [%0], %1, %2, %3, {%4, %4, %4, %4}, p;\n\t"
        "}"
        :: "r"(d_tmem), "l"(a_desc), "l"(b_desc), "r"(idesc), "r"(0u), "r"(en)
        : "memory");
}
#endif

// ============================================================================
// Shared memory layout. K-chunk = 32 (64B rows, SW64). Two pipeline stages.
// Per stage: A_HI 8KB, A_LO 8KB, B_HI 24KB, B_LO 24KB = 64KB.
// All MMA buffers 1024B-aligned.
// ============================================================================
static constexpr int SMEM_TMEMPTR = 0;
static constexpr int SMEM_MBAR0   = 8;     // stage 0 "mma done"
static constexpr int SMEM_MBAR1   = 16;    // stage 1 "mma done"
static constexpr int SMEM_BIAS    = 32;    // 512 floats
static constexpr int SMEM_STAGE0  = 4096;
static constexpr int SMEM_STAGE1  = 69632;
static constexpr int OFF_A_HI     = 0;      // 128 x 64B = 8 KB
static constexpr int OFF_A_LO     = 8192;   // 8 KB
static constexpr int OFF_B_HI     = 16384;  // 384 x 64B = 24 KB
static constexpr int OFF_B_LO     = 40960;  // 24 KB
static constexpr int SMEM_TOTAL   = 135168; // 132 KB

// idesc kind::f16: dtype=F32, atype=btype=BF16, N=128, M=128 (cg1)
static constexpr uint32_t IDESC =
    (1u << 4) | (1u << 7) | (1u << 10) | ((128u / 8) << 17) | ((128u / 16) << 24);

// ============================================================================
// Prep kernel: split fp32 weights into bf16 hi/lo pairs
// ============================================================================
__global__ void __launch_bounds__(256) gru_prep(const float* __restrict__ w_ih,
                                                const float* __restrict__ w_hh) {
    int i = blockIdx.x * 256 + threadIdx.x;
    if (i >= W_ELEMS) return;
    float v = w_ih[i];
    __nv_bfloat16 h = __float2bfloat16(v);
    g_wih_hi[i] = h;
    g_wih_lo[i] = __float2bfloat16(v - __bfloat162float(h));
    v = w_hh[i];
    h = __float2bfloat16(v);
    g_whh_hi[i] = h;
    g_whh_lo[i] = __float2bfloat16(v - __bfloat162float(h));
}

// ============================================================================
// Main fused GRU kernel. One CTA = (u, 128-row batch tile), 256 threads.
// TMEM D layout: [0:128)=r_sum  [128:256)=z_sum  [256:384)=xn  [384:512)=hn
// Pipeline: 8 chunks (2 phases x 4 K32-chunks), 2 smem stages; loads of chunk
// i overlap MMA of chunk i-1 (wait on chunk i-2's commit before buffer reuse).
// ============================================================================
__global__ void __launch_bounds__(256, 1) gru_main(
    const float* __restrict__ inputs,
    const float* __restrict__ hidden,
    const float* __restrict__ w_ih,
    const float* __restrict__ w_hh,
    const float* __restrict__ b_ih,
    const float* __restrict__ b_hh,
    float* __restrict__ out)
{
    extern __shared__ __align__(1024) char smem[];
    const int tid = threadIdx.x;
    const int u   = blockIdx.y;
    const int b0  = blockIdx.x * 128;

#if HAS_TC
    const uint32_t smem_base = smem_to_u32(smem);
    const int wid = tid >> 5;
    const int lid = tid & 31;

    if (wid == 0) {
        TCGEN05_ALLOC(smem_base + SMEM_TMEMPTR, 512);
        TCGEN05_RELINQUISH_ALLOC_PERMIT();
    }
    if (tid == 0) {
        MBARRIER_INIT(smem_base + SMEM_MBAR0, 1);
        MBARRIER_INIT(smem_base + SMEM_MBAR1, 1);
    }

    float* bias = (float*)(smem + SMEM_BIAS);
    for (int g = tid; g < G3; g += 256) {
        float bi = b_ih[u * G3 + g];
        float bh = b_hh[u * G3 + g];
        if (g < 256) {
            bias[g] = bi + bh;          // r,z: biases fold into the summed gate
        } else {
            bias[g]       = bi;         // [256:384) xn bias
            bias[g + 128] = bh;         // [384:512) hn bias
        }
    }
    __syncthreads();

    uint32_t tmem_base;
    asm volatile("ld.shared.b32 %0, [%1];"
                 : "=r"(tmem_base) : "r"(smem_base + SMEM_TMEMPTR));

    // ---------------- pipelined mainloop: 8 chunks ---------------------------
    for (int ch = 0; ch < 8; ch++) {
        const int ph = ch >> 2;          // 0: x-side, 1: h-side
        const int cc = ch & 3;           // K32 chunk within phase
        const int k0 = cc * 32;
        const int s  = ch & 1;
        const int stage = s ? SMEM_STAGE1 : SMEM_STAGE0;
        const uint32_t mbar = smem_base + (s ? SMEM_MBAR1 : SMEM_MBAR0);

        const float* asrc = ph ? hidden : inputs;
        const __nv_bfloat16* wh = ph ? g_whh_hi : g_wih_hi;
        const __nv_bfloat16* wl = ph ? g_whh_lo : g_wih_lo;

        // wait until chunk ch-2 (same stage) MMAs are done before overwrite
        if (ch >= 2) MBARRIER_WAIT_PARITY(mbar, ((ch >> 1) + 1) & 1);

        // A tile: 128 rows x 32 fp32 -> bf16 hi/lo split, SW64 swizzled
        #pragma unroll
        for (int i = 0; i < 4; i++) {
            const int q = tid + i * 256;
            const int row  = q >> 3;
            const int colf = (q & 7) << 2;
            const float4 v = *(const float4*)(asrc +
                (((size_t)(b0 + row)) * U_DIM + u) * I_DIM + k0 + colf);
            __nv_bfloat162 h0 = __float22bfloat162_rn(make_float2(v.x, v.y));
            __nv_bfloat162 h1 = __float22bfloat162_rn(make_float2(v.z, v.w));
            float2 r0 = make_float2(v.x - __bfloat162float(h0.x),
                                    v.y - __bfloat162float(h0.y));
            float2 r1 = make_float2(v.z - __bfloat162float(h1.x),
                                    v.w - __bfloat162float(h1.y));
            __nv_bfloat162 l0 = __float22bfloat162_rn(r0);
            __nv_bfloat162 l1 = __float22bfloat162_rn(r1);
            const uint32_t off = SMEM_SWIZZLE_64B((uint32_t)(row * 64 + colf * 2));
            *(uint2*)(smem + stage + OFF_A_HI + off) =
                make_uint2(*(uint32_t*)&h0, *(uint32_t*)&h1);
            *(uint2*)(smem + stage + OFF_A_LO + off) =
                make_uint2(*(uint32_t*)&l0, *(uint32_t*)&l1);
        }

        // B tile: 384 gate rows x 32 bf16 cols (hi + lo), SW64 swizzled
        #pragma unroll
        for (int i = 0; i < 6; i++) {
            const int q = tid + i * 256;
            const int row = q >> 2;
            const int ce  = (q & 3) << 3;
            const size_t gi = (((size_t)u * G3) + row) * I_DIM + k0 + ce;
            const uint4 vh = *(const uint4*)(wh + gi);
            const uint4 vl = *(const uint4*)(wl + gi);
            const uint32_t off = SMEM_SWIZZLE_64B((uint32_t)(row * 64 + ce * 2));
            *(uint4*)(smem + stage + OFF_B_HI + off) = vh;
            *(uint4*)(smem + stage + OFF_B_LO + off) = vl;
        }

        FENCE_PROXY_ASYNC_SHARED_CTA();
        __syncthreads();

        // MMA issue: 3 split terms x 2 K16 steps x 3 N128 tiles = 18 dispatches
        if (wid == 0) {
            if (elect_one_pred()) {
                const uint32_t sb = smem_base + stage;
                const uint64_t adh = MAKE_SMEM_DESC64(sb + OFF_A_HI);
                const uint64_t adl = MAKE_SMEM_DESC64(sb + OFF_A_LO);
                const uint64_t bdh = MAKE_SMEM_DESC64(sb + OFF_B_HI);
                const uint64_t bdl = MAKE_SMEM_DESC64(sb + OFF_B_LO);
                #pragma unroll
                for (int term = 0; term < 3; term++) {
                    const uint64_t ad = (term == 2) ? adl : adh;
                    const uint64_t bd = (term == 1) ? bdl : bdh;
                    #pragma unroll
                    for (int ks = 0; ks < 2; ks++) {
                        #pragma unroll
                        for (int nt = 0; nt < 3; nt++) {
                            const uint32_t dcol =
                                (ph == 1 && nt == 2) ? 384u : (uint32_t)(nt * 128);
                            const uint32_t first =
                                (cc == 0 && term == 0 && ks == 0) ? 1u : 0u;
                            uint32_t en;
                            if (ph == 0)
                                en = first ? 0u : 1u;          // r,z,xn first touch
                            else
                                en = (nt < 2) ? 1u : (first ? 0u : 1u); // hn first
                            mma_f16_ss(tmem_base + dcol,
                                       ad + ks * 2,
                                       bd + nt * 512 + ks * 2,
                                       IDESC, en);
                        }
                    }
                }
                TCGEN05_COMMIT(mbar);
            }
        }
    }

    // wait for the final commit on each stage (chunks 6 and 7, commit #3 each)
    MBARRIER_WAIT_PARITY(smem_base + SMEM_MBAR0, 1);
    MBARRIER_WAIT_PARITY(smem_base + SMEM_MBAR1, 1);
    TCGEN05_FENCE_AFTER();

    // ---------------- epilogue: TMEM -> GRU elementwise -> GMEM --------------
    // Warps 0-3 handle cols [0,64), warps 4-7 cols [64,128), same row mapping
    // (TMEM subpartition = wid & 3).
    const int row = (wid & 3) * 32 + lid;
    const int c0  = (wid >> 2) * 64;
    const float* hrow = hidden + (((size_t)(b0 + row)) * U_DIM + u) * H_DIM;
    float*       orow = out    + (((size_t)(b0 + row)) * U_DIM + u) * H_DIM;

    for (int cb = c0; cb < c0 + 64; cb += 16) {
        uint32_t rr[16], zz[16], xn[16], hn[16];
        TCGEN05_LD_32X32B_X16(rr, tmem_base + cb);
        TCGEN05_LD_32X32B_X16(zz, tmem_base + 128 + cb);
        TCGEN05_LD_32X32B_X16(xn, tmem_base + 256 + cb);
        TCGEN05_LD_32X32B_X16(hn, tmem_base + 384 + cb);
        TCGEN05_WAIT_LD();

        float4 hv[4];
        const float4* hp = (const float4*)(hrow + cb);
        hv[0] = hp[0]; hv[1] = hp[1]; hv[2] = hp[2]; hv[3] = hp[3];
        const float* hvf = (const float*)hv;

        float res[16];
        #pragma unroll
        for (int j = 0; j < 16; j++) {
            const int c = cb + j;
            const float vr = __uint_as_float(rr[j]) + bias[c];
            const float vz = __uint_as_float(zz[j]) + bias[128 + c];
            const float r  = 1.f / (1.f + __expf(-vr));
            const float z  = 1.f / (1.f + __expf(-vz));
            const float vn = __uint_as_float(xn[j]) + bias[256 + c]
                           + r * (__uint_as_float(hn[j]) + bias[384 + c]);
            const float n  = tanhf(vn);
            res[j] = (1.f - z) * n + z * hvf[j];
        }
        TCGEN05_FENCE_BEFORE();
        float4* op = (float4*)(orow + cb);
        op[0] = ((float4*)res)[0];
        op[1] = ((float4*)res)[1];
        op[2] = ((float4*)res)[2];
        op[3] = ((float4*)res)[3];
    }

    __syncthreads();
    if (wid == 0) {
        TCGEN05_DEALLOC(tmem_base, 512);
    }

#else  // ---------------- fallback: plain fp32 FFMA (non-sm_103a targets) ----
    // Correct but slow; only executes if the runtime ever JITs the plain
    // compute_103 PTX instead of using the sm_103a cubin.
    float* xs = (float*)smem;              // 128 x 128
    float* hs = xs + 128 * 128;            // 128 x 128
    for (int q = tid; q < 128 * 128; q += 256) {
        const int row = q >> 7, col = q & 127;
        const size_t base = (((size_t)(b0 + row)) * U_DIM + u) * I_DIM + col;
        xs[q] = inputs[base];
        hs[q] = hidden[base];
    }
    __syncthreads();

    if (tid < 128) {
        const float* xr_ = xs + tid * 128;
        const float* hr_ = hs + tid * 128;
        float* orow = out + (((size_t)(b0 + tid)) * U_DIM + u) * H_DIM;

        for (int c = 0; c < H_DIM; c++) {
            float axr = b_ih[u * G3 + c],       ahr = b_hh[u * G3 + c];
            float axz = b_ih[u * G3 + 128 + c], ahz = b_hh[u * G3 + 128 + c];
            float axn = b_ih[u * G3 + 256 + c], ahn = b_hh[u * G3 + 256 + c];
            const float* wir = w_ih + (((size_t)u * G3) + c) * I_DIM;
            const float* whr = w_hh + (((size_t)u * G3) + c) * I_DIM;
            for (int k = 0; k < I_DIM; k++) {
                const float xv = xr_[k], hv = hr_[k];
                axr += xv * wir[k];
                axz += xv * wir[128 * I_DIM + k];
                axn += xv * wir[256 * I_DIM + k];
                ahr += hv * whr[k];
                ahz += hv * whr[128 * I_DIM + k];
                ahn += hv * whr[256 * I_DIM + k];
            }
            const float r = 1.f / (1.f + expf(-(axr + ahr)));
            const float z = 1.f / (1.f + expf(-(axz + ahz)));
            const float n = tanhf(axn + r * ahn);
            orow[c] = (1.f - z) * n + z * hr_[c];
        }
    }
#endif
}

// ============================================================================
// kernel_launch — graph-capturable, allocation-free
// ============================================================================
extern "C" void kernel_launch(void* const* d_in, const int* in_sizes, int n_in,
                              void* d_out, int out_size) {
    const float* inputs = (const float*)d_in[0];
    const float* hidden = (const float*)d_in[1];
    const float* w_ih   = (const float*)d_in[2];
    const float* w_hh   = (const float*)d_in[3];
    const float* b_ih   = (const float*)d_in[4];
    const float* b_hh   = (const float*)d_in[5];
    float* out = (float*)d_out;

    const int B = in_sizes[0] / (U_DIM * I_DIM);   // 8192

    gru_prep<<<(W_ELEMS + 255) / 256, 256>>>(w_ih, w_hh);

    cudaFuncSetAttribute(gru_main,
                         cudaFuncAttributeMaxDynamicSharedMemorySize, SMEM_TOTAL);
    gru_main<<<dim3(B / 128, U_DIM), 256, SMEM_TOTAL>>>(
        inputs, hidden, w_ih, w_hh, b_ih, b_hh, out);
}

// round 7
// speedup vs baseline: 1.7953x; 1.0084x over previous
#include <cuda_runtime.h>
#include <cuda_bf16.h>
#include <cstdint>

// ============================================================================
// Arch gating: tcgen05/TMEM are sm_103a ("arch-specific") features. The
// harness also compiles a plain compute_103 stage, which must not see any
// tcgen05 PTX. HAS_TC selects the real tensor-core path only on the
// arch-specific device pass; all other passes get a correct FFMA fallback.
// ============================================================================
#if defined(__CUDA_ARCH__) && \
    (defined(__CUDA_ARCH_FEAT_SM103_ALL) || defined(__CUDA_ARCH_FEAT_SM100_ALL) || \
     defined(__CUDA_ARCH_SPECIFIC__) || defined(__CUDA_ARCH_FAMILY_SPECIFIC__))
#define HAS_TC 1
#else
#define HAS_TC 0
#endif

// ============================================================================
// Problem constants: B=8192 (derived at launch), U=16, I=H=128, 3H=384 gates
// ============================================================================
#define U_DIM 16
#define I_DIM 128
#define H_DIM 128
#define G3    384
#define W_ELEMS (U_DIM * G3 * I_DIM)   // 786432 per weight matrix

// Pre-split weights (fp32 -> bf16 hi + bf16 lo), filled by prep kernel.
__device__ __nv_bfloat16 g_wih_hi[W_ELEMS];
__device__ __nv_bfloat16 g_wih_lo[W_ELEMS];
__device__ __nv_bfloat16 g_whh_hi[W_ELEMS];
__device__ __nv_bfloat16 g_whh_lo[W_ELEMS];

// ============================================================================
// PTX helpers
// ============================================================================
__device__ __forceinline__ uint32_t elect_one_pred() {
    uint32_t pred;
    asm volatile(
        "{\n\t"
        ".reg .pred p;\n\t"
        "elect.sync _|p, 0xFFFFFFFF;\n\t"
        "selp.b32 %0, 1, 0, p;\n\t"
        "}"
        : "=r"(pred));
    return pred;
}

__device__ __forceinline__ uint32_t smem_to_u32(const void* smem_ptr) {
    uint32_t addr;
    asm("{ .reg .u64 tmp; cvta.to.shared.u64 tmp, %1; cvt.u32.u64 %0, tmp; }"
        : "=r"(addr) : "l"(smem_ptr));
    return addr;
}

// SW64 swizzle: atom = 8 rows x 64 bytes
#define SMEM_SWIZZLE_64B(byte_offset) \
    ((byte_offset) ^ (((byte_offset) >> 3) & 0x30))

// SW64 smem descriptor: layout=4, version=1 (Blackwell), SBO=32 (512B per
// 8-row group), LBO=1 (16B inner stride). Rows are 64B wide.
static constexpr uint64_t SMEM_DESC_BASE_SW64 =
    (uint64_t(4)  << 61)
    | (uint64_t(1) << 46)
    | (uint64_t(32) << 32)
    | (uint64_t(1) << 16);

#define MAKE_SMEM_DESC64(base_addr) \
    (SMEM_DESC_BASE_SW64 | ((uint64_t)((base_addr) >> 4) & 0x3FFF))

#define TCGEN05_ALLOC(smem_result_addr, nCols) \
    asm volatile( \
        "tcgen05.alloc.cta_group::1.sync.aligned.shared::cta.b32 [%0], %1;" \
        :: "r"((uint32_t)(smem_result_addr)), "r"((uint32_t)(nCols)) \
        : "memory")

#define TCGEN05_DEALLOC(tmem_addr, nCols) \
    asm volatile( \
        "tcgen05.dealloc.cta_group::1.sync.aligned.b32 %0, %1;" \
        :: "r"(tmem_addr), "r"((uint32_t)(nCols)))

#define TCGEN05_RELINQUISH_ALLOC_PERMIT() \
    asm volatile("tcgen05.relinquish_alloc_permit.cta_group::1.sync.aligned;")

#define TCGEN05_COMMIT(mbar_smem_addr) \
    asm volatile( \
        "tcgen05.commit.cta_group::1.mbarrier::arrive::one.shared::cluster.b64 [%0];" \
        :: "r"((uint32_t)(mbar_smem_addr)) \
        : "memory")

#define TCGEN05_FENCE_AFTER() \
    asm volatile("tcgen05.fence::after_thread_sync;" ::: "memory")

#define TCGEN05_FENCE_BEFORE() \
    asm volatile("tcgen05.fence::before_thread_sync;" ::: "memory")

#define TCGEN05_WAIT_LD() \
    asm volatile("tcgen05.wait::ld.sync.aligned;" ::: "memory")

#define FENCE_PROXY_ASYNC_SHARED_CTA() \
    asm volatile("fence.proxy.async.shared::cta;" ::: "memory")

#define MBARRIER_INIT(mbar_smem_addr, count) \
    asm volatile( \
        "mbarrier.init.shared.b64 [%0], %1;" \
        :: "r"((uint32_t)(mbar_smem_addr)), "r"((uint32_t)(count)) \
        : "memory")

#define MBARRIER_WAIT_PARITY(mbar_smem_addr, phase_parity) do { \
    uint32_t _mbar = (uint32_t)(mbar_smem_addr); \
    uint32_t _parity = (uint32_t)(phase_parity); \
    uint32_t _done; \
    asm volatile( \
        "{\n\t" \
        ".reg .pred p;\n\t" \
        "mbarrier.try_wait.parity.acquire.cta.shared::cta.b64 p, [%1], %2;\n\t" \
        "selp.b32 %0, 1, 0, p;\n\t" \
        "}" \
        : "=r"(_done) : "r"(_mbar), "r"(_parity) : "memory"); \
    if (!_done) { \
        asm volatile( \
            "{\n\t" \
            ".reg .pred P1;\n\t" \
            "WAIT_LOOP_%=:\n\t" \
            "mbarrier.try_wait.parity.acquire.cta.shared::cta.b64 P1, [%0], %1, 0x989680;\n\t" \
            "@P1 bra.uni WAIT_DONE_%=;\n\t" \
            "bra.uni WAIT_LOOP_%=;\n\t" \
            "WAIT_DONE_%=:\n\t" \
            "}" \
            :: "r"(_mbar), "r"(_parity) : "memory"); \
    } \
} while(0)

#define TCGEN05_LD_32X32B_X16(r, tmem_addr) \
    asm volatile( \
        "tcgen05.ld.sync.aligned.32x32b.x16.b32 " \
        "{%0, %1, %2, %3, %4, %5, %6, %7, " \
        " %8, %9, %10, %11, %12, %13, %14, %15}, [%16];" \
        : "=r"((r)[0]),  "=r"((r)[1]),  "=r"((r)[2]),  "=r"((r)[3]), \
          "=r"((r)[4]),  "=r"((r)[5]),  "=r"((r)[6]),  "=r"((r)[7]), \
          "=r"((r)[8]),  "=r"((r)[9]),  "=r"((r)[10]), "=r"((r)[11]), \
          "=r"((r)[12]), "=r"((r)[13]), "=r"((r)[14]), "=r"((r)[15]) \
        : "r"(tmem_addr))

#if HAS_TC
// SS-mode cg1 bf16 MMA (kind::f16), fp32 accumulate in TMEM.
__device__ __forceinline__ void mma_f16_ss(uint32_t d_tmem, uint64_t a_desc,
                                           uint64_t b_desc, uint32_t idesc,
                                           uint32_t en) {
    asm volatile(
        "{\n\t"
        ".reg .pred p;\n\t"
        "setp.ne.u32 p, %5, 0;\n\t"
        "tcgen05.mma.cta_group::1.kind::f16 [%0], %1, %2, %3, {%4, %4, %4, %4}, p;\n\t"
        "}"
        :: "r"(d_tmem), "l"(a_desc), "l"(b_desc), "r"(idesc), "r"(0u), "r"(en)
        : "memory");
}
#endif

// ============================================================================
// Shared memory layout. K-chunk = 32 (64B rows, SW64). Two pipeline stages.
// Per stage: A_HI 8KB, A_LO 8KB, B_HI 24KB, B_LO 24KB = 64KB.
// All MMA buffers 1024B-aligned.
// ============================================================================
static constexpr int SMEM_TMEMPTR = 0;
static constexpr int SMEM_MBAR0   = 8;     // stage 0 "mma done"
static constexpr int SMEM_MBAR1   = 16;    // stage 1 "mma done"
static constexpr int SMEM_BIAS    = 32;    // 512 floats
static constexpr int SMEM_STAGE0  = 4096;
static constexpr int SMEM_STAGE1  = 69632;
static constexpr int OFF_A_HI     = 0;      // 128 x 64B = 8 KB
static constexpr int OFF_A_LO     = 8192;   // 8 KB
static constexpr int OFF_B_HI     = 16384;  // 384 x 64B = 24 KB
static constexpr int OFF_B_LO     = 40960;  // 24 KB
static constexpr int SMEM_TOTAL   = 135168; // 132 KB

// idesc kind::f16: dtype=F32, atype=btype=BF16, N=128, M=128 (cg1)
static constexpr uint32_t IDESC =
    (1u << 4) | (1u << 7) | (1u << 10) | ((128u / 8) << 17) | ((128u / 16) << 24);

// ============================================================================
// Prep kernel: split fp32 weights into bf16 hi/lo pairs
// ============================================================================
__global__ void __launch_bounds__(256) gru_prep(const float* __restrict__ w_ih,
                                                const float* __restrict__ w_hh) {
    int i = blockIdx.x * 256 + threadIdx.x;
    if (i >= W_ELEMS) return;
    float v = w_ih[i];
    __nv_bfloat16 h = __float2bfloat16(v);
    g_wih_hi[i] = h;
    g_wih_lo[i] = __float2bfloat16(v - __bfloat162float(h));
    v = w_hh[i];
    h = __float2bfloat16(v);
    g_whh_hi[i] = h;
    g_whh_lo[i] = __float2bfloat16(v - __bfloat162float(h));
}

// ============================================================================
// Main fused GRU kernel. One CTA = (u, 128-row batch tile), 256 threads.
// TMEM D layout: [0:128)=r_sum  [128:256)=z_sum  [256:384)=xn  [384:512)=hn
// Pipeline: 8 chunks (2 phases x 4 K32-chunks), 2 smem stages; loads of chunk
// i overlap MMA of chunk i-1 (wait on chunk i-2's commit before buffer reuse).
// ============================================================================
__global__ void __launch_bounds__(256, 1) gru_main(
    const float* __restrict__ inputs,
    const float* __restrict__ hidden,
    const float* __restrict__ w_ih,
    const float* __restrict__ w_hh,
    const float* __restrict__ b_ih,
    const float* __restrict__ b_hh,
    float* __restrict__ out)
{
    extern __shared__ __align__(1024) char smem[];
    const int tid = threadIdx.x;
    const int u   = blockIdx.y;
    const int b0  = blockIdx.x * 128;

#if HAS_TC
    const uint32_t smem_base = smem_to_u32(smem);
    const int wid = tid >> 5;
    const int lid = tid & 31;

    if (wid == 0) {
        TCGEN05_ALLOC(smem_base + SMEM_TMEMPTR, 512);
        TCGEN05_RELINQUISH_ALLOC_PERMIT();
    }
    if (tid == 0) {
        MBARRIER_INIT(smem_base + SMEM_MBAR0, 1);
        MBARRIER_INIT(smem_base + SMEM_MBAR1, 1);
    }

    float* bias = (float*)(smem + SMEM_BIAS);
    for (int g = tid; g < G3; g += 256) {
        float bi = b_ih[u * G3 + g];
        float bh = b_hh[u * G3 + g];
        if (g < 256) {
            bias[g] = bi + bh;          // r,z: biases fold into the summed gate
        } else {
            bias[g]       = bi;         // [256:384) xn bias
            bias[g + 128] = bh;         // [384:512) hn bias
        }
    }
    __syncthreads();

    uint32_t tmem_base;
    asm volatile("ld.shared.b32 %0, [%1];"
                 : "=r"(tmem_base) : "r"(smem_base + SMEM_TMEMPTR));

    // ---------------- pipelined mainloop: 8 chunks ---------------------------
    for (int ch = 0; ch < 8; ch++) {
        const int ph = ch >> 2;          // 0: x-side, 1: h-side
        const int cc = ch & 3;           // K32 chunk within phase
        const int k0 = cc * 32;
        const int s  = ch & 1;
        const int stage = s ? SMEM_STAGE1 : SMEM_STAGE0;
        const uint32_t mbar = smem_base + (s ? SMEM_MBAR1 : SMEM_MBAR0);

        const float* asrc = ph ? hidden : inputs;
        const __nv_bfloat16* wh = ph ? g_whh_hi : g_wih_hi;
        const __nv_bfloat16* wl = ph ? g_whh_lo : g_wih_lo;

        // wait until chunk ch-2 (same stage) MMAs are done before overwrite
        if (ch >= 2) MBARRIER_WAIT_PARITY(mbar, ((ch >> 1) + 1) & 1);

        // A tile: 128 rows x 32 fp32 -> bf16 hi/lo split, SW64 swizzled
        #pragma unroll
        for (int i = 0; i < 4; i++) {
            const int q = tid + i * 256;
            const int row  = q >> 3;
            const int colf = (q & 7) << 2;
            const float4 v = *(const float4*)(asrc +
                (((size_t)(b0 + row)) * U_DIM + u) * I_DIM + k0 + colf);
            __nv_bfloat162 h0 = __float22bfloat162_rn(make_float2(v.x, v.y));
            __nv_bfloat162 h1 = __float22bfloat162_rn(make_float2(v.z, v.w));
            float2 r0 = make_float2(v.x - __bfloat162float(h0.x),
                                    v.y - __bfloat162float(h0.y));
            float2 r1 = make_float2(v.z - __bfloat162float(h1.x),
                                    v.w - __bfloat162float(h1.y));
            __nv_bfloat162 l0 = __float22bfloat162_rn(r0);
            __nv_bfloat162 l1 = __float22bfloat162_rn(r1);
            const uint32_t off = SMEM_SWIZZLE_64B((uint32_t)(row * 64 + colf * 2));
            *(uint2*)(smem + stage + OFF_A_HI + off) =
                make_uint2(*(uint32_t*)&h0, *(uint32_t*)&h1);
            *(uint2*)(smem + stage + OFF_A_LO + off) =
                make_uint2(*(uint32_t*)&l0, *(uint32_t*)&l1);
        }

        // B tile: 384 gate rows x 32 bf16 cols (hi + lo), SW64 swizzled
        #pragma unroll
        for (int i = 0; i < 6; i++) {
            const int q = tid + i * 256;
            const int row = q >> 2;
            const int ce  = (q & 3) << 3;
            const size_t gi = (((size_t)u * G3) + row) * I_DIM + k0 + ce;
            const uint4 vh = *(const uint4*)(wh + gi);
            const uint4 vl = *(const uint4*)(wl + gi);
            const uint32_t off = SMEM_SWIZZLE_64B((uint32_t)(row * 64 + ce * 2));
            *(uint4*)(smem + stage + OFF_B_HI + off) = vh;
            *(uint4*)(smem + stage + OFF_B_LO + off) = vl;
        }

        FENCE_PROXY_ASYNC_SHARED_CTA();
        __syncthreads();

        // MMA issue: 3 split terms x 2 K16 steps x 3 N128 tiles = 18 dispatches
        if (wid == 0) {
            if (elect_one_pred()) {
                const uint32_t sb = smem_base + stage;
                const uint64_t adh = MAKE_SMEM_DESC64(sb + OFF_A_HI);
                const uint64_t adl = MAKE_SMEM_DESC64(sb + OFF_A_LO);
                const uint64_t bdh = MAKE_SMEM_DESC64(sb + OFF_B_HI);
                const uint64_t bdl = MAKE_SMEM_DESC64(sb + OFF_B_LO);
                #pragma unroll
                for (int term = 0; term < 3; term++) {
                    const uint64_t ad = (term == 2) ? adl : adh;
                    const uint64_t bd = (term == 1) ? bdl : bdh;
                    #pragma unroll
                    for (int ks = 0; ks < 2; ks++) {
                        #pragma unroll
                        for (int nt = 0; nt < 3; nt++) {
                            const uint32_t dcol =
                                (ph == 1 && nt == 2) ? 384u : (uint32_t)(nt * 128);
                            const uint32_t first =
                                (cc == 0 && term == 0 && ks == 0) ? 1u : 0u;
                            uint32_t en;
                            if (ph == 0)
                                en = first ? 0u : 1u;          // r,z,xn first touch
                            else
                                en = (nt < 2) ? 1u : (first ? 0u : 1u); // hn first
                            mma_f16_ss(tmem_base + dcol,
                                       ad + ks * 2,
                                       bd + nt * 512 + ks * 2,
                                       IDESC, en);
                        }
                    }
                }
                TCGEN05_COMMIT(mbar);
            }
        }
    }

    // wait for the final commit on each stage (chunks 6 and 7, commit #3 each)
    MBARRIER_WAIT_PARITY(smem_base + SMEM_MBAR0, 1);
    MBARRIER_WAIT_PARITY(smem_base + SMEM_MBAR1, 1);
    TCGEN05_FENCE_AFTER();

    // ---------------- epilogue: TMEM -> GRU elementwise -> GMEM --------------
    // Warps 0-3 handle cols [0,64), warps 4-7 cols [64,128), same row mapping
    // (TMEM subpartition = wid & 3).
    const int row = (wid & 3) * 32 + lid;
    const int c0  = (wid >> 2) * 64;
    const float* hrow = hidden + (((size_t)(b0 + row)) * U_DIM + u) * H_DIM;
    float*       orow = out    + (((size_t)(b0 + row)) * U_DIM + u) * H_DIM;

    for (int cb = c0; cb < c0 + 64; cb += 16) {
        uint32_t rr[16], zz[16], xn[16], hn[16];
        TCGEN05_LD_32X32B_X16(rr, tmem_base + cb);
        TCGEN05_LD_32X32B_X16(zz, tmem_base + 128 + cb);
        TCGEN05_LD_32X32B_X16(xn, tmem_base + 256 + cb);
        TCGEN05_LD_32X32B_X16(hn, tmem_base + 384 + cb);
        TCGEN05_WAIT_LD();

        float4 hv[4];
        const float4* hp = (const float4*)(hrow + cb);
        hv[0] = hp[0]; hv[1] = hp[1]; hv[2] = hp[2]; hv[3] = hp[3];
        const float* hvf = (const float*)hv;

        float res[16];
        #pragma unroll
        for (int j = 0; j < 16; j++) {
            const int c = cb + j;
            const float vr = __uint_as_float(rr[j]) + bias[c];
            const float vz = __uint_as_float(zz[j]) + bias[128 + c];
            const float r  = 1.f / (1.f + __expf(-vr));
            const float z  = 1.f / (1.f + __expf(-vz));
            const float vn = __uint_as_float(xn[j]) + bias[256 + c]
                           + r * (__uint_as_float(hn[j]) + bias[384 + c]);
            const float n  = tanhf(vn);
            res[j] = (1.f - z) * n + z * hvf[j];
        }
        TCGEN05_FENCE_BEFORE();
        float4* op = (float4*)(orow + cb);
        op[0] = ((float4*)res)[0];
        op[1] = ((float4*)res)[1];
        op[2] = ((float4*)res)[2];
        op[3] = ((float4*)res)[3];
    }

    __syncthreads();
    if (wid == 0) {
        TCGEN05_DEALLOC(tmem_base, 512);
    }

#else  // ---------------- fallback: plain fp32 FFMA (non-sm_103a targets) ----
    // Correct but slow; only executes if the runtime ever JITs the plain
    // compute_103 PTX instead of using the sm_103a cubin.
    float* xs = (float*)smem;              // 128 x 128
    float* hs = xs + 128 * 128;            // 128 x 128
    for (int q = tid; q < 128 * 128; q += 256) {
        const int row = q >> 7, col = q & 127;
        const size_t base = (((size_t)(b0 + row)) * U_DIM + u) * I_DIM + col;
        xs[q] = inputs[base];
        hs[q] = hidden[base];
    }
    __syncthreads();

    if (tid < 128) {
        const float* xr_ = xs + tid * 128;
        const float* hr_ = hs + tid * 128;
        float* orow = out + (((size_t)(b0 + tid)) * U_DIM + u) * H_DIM;

        for (int c = 0; c < H_DIM; c++) {
            float axr = b_ih[u * G3 + c],       ahr = b_hh[u * G3 + c];
            float axz = b_ih[u * G3 + 128 + c], ahz = b_hh[u * G3 + 128 + c];
            float axn = b_ih[u * G3 + 256 + c], ahn = b_hh[u * G3 + 256 + c];
            const float* wir = w_ih + (((size_t)u * G3) + c) * I_DIM;
            const float* whr = w_hh + (((size_t)u * G3) + c) * I_DIM;
            for (int k = 0; k < I_DIM; k++) {
                const float xv = xr_[k], hv = hr_[k];
                axr += xv * wir[k];
                axz += xv * wir[128 * I_DIM + k];
                axn += xv * wir[256 * I_DIM + k];
                ahr += hv * whr[k];
                ahz += hv * whr[128 * I_DIM + k];
                ahn += hv * whr[256 * I_DIM + k];
            }
            const float r = 1.f / (1.f + expf(-(axr + ahr)));
            const float z = 1.f / (1.f + expf(-(axz + ahz)));
            const float n = tanhf(axn + r * ahn);
            orow[c] = (1.f - z) * n + z * hr_[c];
        }
    }
#endif
}

// ============================================================================
// kernel_launch — graph-capturable, allocation-free
// ============================================================================
extern "C" void kernel_launch(void* const* d_in, const int* in_sizes, int n_in,
                              void* d_out, int out_size) {
    const float* inputs = (const float*)d_in[0];
    const float* hidden = (const float*)d_in[1];
    const float* w_ih   = (const float*)d_in[2];
    const float* w_hh   = (const float*)d_in[3];
    const float* b_ih   = (const float*)d_in[4];
    const float* b_hh   = (const float*)d_in[5];
    float* out = (float*)d_out;

    const int B = in_sizes[0] / (U_DIM * I_DIM);   // 8192

    gru_prep<<<(W_ELEMS + 255) / 256, 256>>>(w_ih, w_hh);

    cudaFuncSetAttribute(gru_main,
                         cudaFuncAttributeMaxDynamicSharedMemorySize, SMEM_TOTAL);
    gru_main<<<dim3(B / 128, U_DIM), 256, SMEM_TOTAL>>>(
        inputs, hidden, w_ih, w_hh, b_ih, b_hh, out);
}